// round 2
// baseline (speedup 1.0000x reference)
#include <cuda_runtime.h>
#include <cuda_bf16.h>
#include <math.h>

#define B_ 4
#define T_ 8192
#define BT_ (B_*T_)
#define NP_ 64
#define EPS_RADIUS 0.001f
#define NIT 72

// ---------------- device scratch (no allocs allowed) ----------------
__device__ float g_Kfull[8*256*256];
__device__ float g_G[8*256*256];
__device__ float g_lambda[8];
__device__ float g_scaleArr[2];
__device__ float g_pairs[NP_*3];   // rho, cos, sin
__device__ float g_a[NP_*2];       // a = rho e^{i theta} / scale
__device__ float g_aL[NP_*2];      // a^128
__device__ float g_pi[(size_t)BT_*8];
__device__ float g_vraw[(size_t)BT_*128];
__device__ float g_W[4*64*64*2];
__device__ float g_pref[4*64*64*2];

// ---------------- reductions ----------------
__device__ __forceinline__ float blkSum(float v, volatile float* red, int tid) {
    #pragma unroll
    for (int o = 16; o; o >>= 1) v += __shfl_xor_sync(0xffffffffu, v, o);
    if ((tid & 31) == 0) red[tid >> 5] = v;
    __syncthreads();
    float r = red[0]+red[1]+red[2]+red[3]+red[4]+red[5]+red[6]+red[7];
    __syncthreads();
    return r;
}
__device__ __forceinline__ float blkMax(float v, volatile float* red, int tid) {
    #pragma unroll
    for (int o = 16; o; o >>= 1) v = fmaxf(v, __shfl_xor_sync(0xffffffffu, v, o));
    if ((tid & 31) == 0) red[tid >> 5] = v;
    __syncthreads();
    float r = red[0];
    #pragma unroll
    for (int k = 1; k < 8; k++) r = fmaxf(r, red[k]);
    __syncthreads();
    return r;
}

// ---------------- 1: pair params ----------------
__global__ void k_pairs(const float* __restrict__ rho_raw, const float* __restrict__ theta) {
    int i = threadIdx.x;
    if (i < NP_) {
        float t = 1.f / (1.f + expf(-rho_raw[i]));
        g_pairs[i*3+0] = t * (1.0f - EPS_RADIUS);
        g_pairs[i*3+1] = cosf(theta[i]);
        g_pairs[i*3+2] = sinf(theta[i]);
    }
}

// ---------------- 2: assemble K_raw ----------------
__global__ __launch_bounds__(256) void k_build(const float* __restrict__ K12,
                                               const float* __restrict__ K21,
                                               const float* __restrict__ K22) {
    int e = blockIdx.x;
    int tid = threadIdx.x;
    for (int r = 0; r < 256; r++) {
        int idx = tid + (r << 8);
        int row = idx >> 8;
        int col = idx & 255;
        float val;
        if (row < 128) {
            if (col < 128) {
                val = 0.f;
                int pr = row >> 1;
                if ((col >> 1) == pr) {
                    float rho = g_pairs[pr*3], c = g_pairs[pr*3+1], s = g_pairs[pr*3+2];
                    int ai = row & 1, bi = col & 1;
                    val = (ai == 0) ? (bi == 0 ? rho*c : -rho*s)
                                    : (bi == 0 ? rho*s :  rho*c);
                }
            } else {
                val = K12[((size_t)(e*128 + row) << 7) + (col - 128)];
            }
        } else {
            int r2 = row - 128;
            val = (col < 128) ? K21[((size_t)(e*128 + r2) << 7) + col]
                              : K22[((size_t)(e*128 + r2) << 7) + (col - 128)];
        }
        g_Kfull[((size_t)e << 16) + idx] = val;
    }
}

// ---------------- 3: G = K K^T (32x32 tiles, K-slab 64) ----------------
__global__ __launch_bounds__(256) void k_G() {
    __shared__ float sA[32*68], sB[32*68];
    int e = blockIdx.y;
    int ti = blockIdx.x >> 3, tj = blockIdx.x & 7;
    int tid = threadIdx.x;
    const float* Kb = g_Kfull + ((size_t)e << 16);
    int i0 = (tid >> 4) * 2, j0 = (tid & 15) * 2;
    float a00=0.f,a01=0.f,a10=0.f,a11=0.f;
    for (int ks = 0; ks < 4; ks++) {
        __syncthreads();
        #pragma unroll
        for (int r = 0; r < 8; r++) {
            int idx = tid + (r << 8);
            int row = idx >> 6, kk = idx & 63;
            sA[row*68+kk] = Kb[(ti*32+row)*256 + ks*64+kk];
            sB[row*68+kk] = Kb[(tj*32+row)*256 + ks*64+kk];
        }
        __syncthreads();
        #pragma unroll 16
        for (int kk = 0; kk < 64; kk++) {
            float x0 = sA[i0*68+kk],     x1 = sA[(i0+1)*68+kk];
            float y0 = sB[j0*68+kk],     y1 = sB[(j0+1)*68+kk];
            a00 = fmaf(x0,y0,a00); a01 = fmaf(x0,y1,a01);
            a10 = fmaf(x1,y0,a10); a11 = fmaf(x1,y1,a11);
        }
    }
    float* Gb = g_G + ((size_t)e << 16);
    Gb[(ti*32+i0  )*256 + tj*32+j0  ] = a00;
    Gb[(ti*32+i0  )*256 + tj*32+j0+1] = a01;
    Gb[(ti*32+i0+1)*256 + tj*32+j0  ] = a10;
    Gb[(ti*32+i0+1)*256 + tj*32+j0+1] = a11;
}

// ---------------- 4: Lanczos + Sturm bisection for lambda_max(G) ----------------
__global__ __launch_bounds__(256) void k_lanczos() {
    __shared__ __align__(16) float sv[256];
    __shared__ float red[8];
    __shared__ float salpha[NIT], sbeta[NIT];
    int e = blockIdx.x;
    int tid = threadIdx.x;
    const float* Gb = g_G + ((size_t)e << 16);

    unsigned h = (unsigned)tid * 2654435761u ^ ((unsigned)e * 0x9E3779B9u);
    h ^= h >> 13; h *= 0x85ebca6bu; h ^= h >> 16;
    float v = (float)(h & 0xFFFFu) * (1.0f/65536.0f) - 0.5f + 0.0078125f;
    float nr = sqrtf(blkSum(v*v, red, tid));
    v /= nr;
    sv[tid] = v;
    float vprev = 0.f, betap = 0.f;
    int n = NIT;
    for (int it = 0; it < NIT; it++) {
        __syncthreads();
        const float4* row = (const float4*)(Gb + (size_t)tid * 256);
        const float4* sp  = (const float4*)sv;
        float gv = 0.f;
        #pragma unroll 16
        for (int q = 0; q < 64; q++) {
            float4 g = row[q], s = sp[q];
            gv = fmaf(g.x,s.x,gv); gv = fmaf(g.y,s.y,gv);
            gv = fmaf(g.z,s.z,gv); gv = fmaf(g.w,s.w,gv);
        }
        float w = gv - betap * vprev;
        float al = blkSum(v * w, red, tid);
        w -= al * v;
        float b2 = blkSum(w * w, red, tid);
        float bet = sqrtf(b2);
        if (tid == 0) { salpha[it] = al; sbeta[it] = bet; }
        if (bet < 1e-12f) { n = it + 1; break; }
        vprev = v; betap = bet;
        v = w / bet;
        sv[tid] = v;
    }
    __syncthreads();
    float hi = 0.f;
    for (int k = tid; k < n; k += 256) {
        float b0 = (k > 0)     ? sbeta[k-1] : 0.f;
        float b1 = (k < n - 1) ? sbeta[k]   : 0.f;
        hi = fmaxf(hi, salpha[k] + b0 + b1);
    }
    hi = blkMax(hi, red, tid) * 1.0001f + 1e-6f;
    float lo = 0.f;
    for (int round = 0; round < 3; round++) {
        float x = lo + (hi - lo) * ((float)(tid + 1) * (1.0f/257.0f));
        int cnt = 0;
        float d = 1.f;
        for (int k = 0; k < n; k++) {
            float bb = (k > 0) ? sbeta[k-1] : 0.f;
            d = (salpha[k] - x) - bb*bb/d;
            if (d < 0.f) cnt++;
            if (fabsf(d) < 1e-25f) d = -1e-25f;
        }
        float nlo = (cnt <  n) ? x : lo;
        float nhi = (cnt >= n) ? x : hi;
        lo = blkMax(nlo, red, tid);
        hi = -blkMax(-nhi, red, tid);
    }
    if (tid == 0) g_lambda[e] = 0.5f * (lo + hi);
}

// ---------------- 5: scale + scaled poles + a^128 ----------------
__global__ void k_scale() {
    int i = threadIdx.x;
    float s = 1.0f;
    #pragma unroll
    for (int e = 0; e < 8; e++) s = fmaxf(s, sqrtf(g_lambda[e]));
    if (i == 0) { g_scaleArr[0] = s; g_scaleArr[1] = 1.f / s; }
    if (i < NP_) {
        float inv = 1.f / s;
        float rho = g_pairs[i*3], c = g_pairs[i*3+1], sn = g_pairs[i*3+2];
        float ax = rho * c * inv, ay = rho * sn * inv;
        g_a[i*2+0] = ax; g_a[i*2+1] = ay;
        float px = ax, py = ay;
        #pragma unroll
        for (int q = 0; q < 7; q++) { float nx = px*px - py*py, ny = 2.f*px*py; px = nx; py = ny; }
        g_aL[i*2+0] = px; g_aL[i*2+1] = py;
    }
}

// ---------------- 6: gating softmax ----------------
__global__ __launch_bounds__(256) void k_gate(const float* __restrict__ u,
                                              const float* __restrict__ gw,
                                              const float* __restrict__ gb) {
    __shared__ __align__(16) float sgw[1024];
    __shared__ float sgb[8];
    int tid = threadIdx.x;
    #pragma unroll
    for (int r = 0; r < 4; r++) sgw[tid + (r << 8)] = gw[tid + (r << 8)];
    if (tid < 8) sgb[tid] = gb[tid];
    __syncthreads();
    int tok = blockIdx.x * 32 + (tid >> 3);
    int m = tid & 7;
    const float4* ur = (const float4*)(u + ((size_t)tok << 7));
    const float4* wr = (const float4*)(sgw + (m << 7));
    float acc = sgb[m];
    #pragma unroll 8
    for (int q = 0; q < 32; q++) {
        float4 a = ur[q], w = wr[q];
        acc = fmaf(a.x, w.x, acc); acc = fmaf(a.y, w.y, acc);
        acc = fmaf(a.z, w.z, acc); acc = fmaf(a.w, w.w, acc);
    }
    float mx = acc;
    #pragma unroll
    for (int o = 4; o; o >>= 1) mx = fmaxf(mx, __shfl_xor_sync(0xffffffffu, mx, o));
    float ex = expf(acc - mx);
    float sm = ex;
    #pragma unroll
    for (int o = 4; o; o >>= 1) sm += __shfl_xor_sync(0xffffffffu, sm, o);
    g_pi[(size_t)tok * 8 + m] = ex / sm;
}

// ---------------- 7: v-GEMM  v[t][s] = inv * sum_m pi[t,m] sum_j K12[m][s][j] u[t][j] ----------------
__global__ __launch_bounds__(256, 2) void k_vgemm(const float* __restrict__ u,
                                                  const float* __restrict__ K12) {
    __shared__ float sxT[32*68];
    __shared__ float sK[32*132];
    int tid = threadIdx.x;
    int tok0 = blockIdx.x * 64;
    float inv = g_scaleArr[1];
    int s0 = (tid >> 4) * 8;
    int t0 = (tid & 15) * 4;
    float acc[4][8] = {};
    for (int jt = 0; jt < 4; jt++) {
        __syncthreads();
        #pragma unroll
        for (int r = 0; r < 8; r++) {
            int idx = tid + (r << 8);
            int jl = idx & 31, t = idx >> 5;
            sxT[jl*68 + t] = u[((size_t)(tok0 + t) << 7) + jt*32 + jl];
        }
        for (int m = 0; m < 8; m++) {
            __syncthreads();
            #pragma unroll
            for (int r = 0; r < 16; r++) {
                int idx = tid + (r << 8);
                int jl = idx & 31, s = idx >> 5;
                sK[jl*132 + s] = K12[((size_t)(m*128 + s) << 7) + jt*32 + jl];
            }
            __syncthreads();
            float part[4][8] = {};
            #pragma unroll 8
            for (int jl = 0; jl < 32; jl++) {
                float4 xv = *(const float4*)&sxT[jl*68 + t0];
                float4 k0 = *(const float4*)&sK[jl*132 + s0];
                float4 k1 = *(const float4*)&sK[jl*132 + s0 + 4];
                float xs[4] = {xv.x, xv.y, xv.z, xv.w};
                float ks[8] = {k0.x,k0.y,k0.z,k0.w,k1.x,k1.y,k1.z,k1.w};
                #pragma unroll
                for (int tt = 0; tt < 4; tt++)
                    #pragma unroll
                    for (int ii = 0; ii < 8; ii++)
                        part[tt][ii] = fmaf(xs[tt], ks[ii], part[tt][ii]);
            }
            #pragma unroll
            for (int tt = 0; tt < 4; tt++) {
                float p = g_pi[(size_t)(tok0 + t0 + tt) * 8 + m];
                #pragma unroll
                for (int ii = 0; ii < 8; ii++)
                    acc[tt][ii] = fmaf(p, part[tt][ii], acc[tt][ii]);
            }
        }
    }
    #pragma unroll
    for (int tt = 0; tt < 4; tt++) {
        float* o = g_vraw + ((size_t)(tok0 + t0 + tt) << 7) + s0;
        float4 w0 = {acc[tt][0]*inv, acc[tt][1]*inv, acc[tt][2]*inv, acc[tt][3]*inv};
        float4 w1 = {acc[tt][4]*inv, acc[tt][5]*inv, acc[tt][6]*inv, acc[tt][7]*inv};
        *(float4*)o = w0;
        *(float4*)(o + 4) = w1;
    }
}

// ---------------- 8-10: chunked complex scan (L=128, C=64) ----------------
__global__ __launch_bounds__(64) void k_scan1() {
    int b = blockIdx.x >> 6, ch = blockIdx.x & 63;
    int p = threadIdx.x;
    float ax = g_a[p*2], ay = g_a[p*2+1];
    float cx = 0.f, cy = 0.f;
    const float* base = g_vraw + (((size_t)b*T_ + ch*128) << 7) + 2*p;
    for (int k = 0; k < 128; k++) {
        float2 w = *(const float2*)(base + (size_t)k*128);
        float nx = fmaf(ax, cx, fmaf(-ay, cy, w.x));
        float ny = fmaf(ax, cy, fmaf( ay, cx, w.y));
        cx = nx; cy = ny;
    }
    ((float2*)g_W)[(b*64 + ch)*64 + p] = make_float2(cx, cy);
}

__global__ __launch_bounds__(256) void k_scan2() {
    int tid = threadIdx.x;
    int b = tid >> 6, p = tid & 63;
    float ax = g_aL[p*2], ay = g_aL[p*2+1];
    float cx = 0.f, cy = 0.f;
    float2* W = (float2*)g_W;
    float2* P = (float2*)g_pref;
    for (int ch = 0; ch < 64; ch++) {
        int idx = (b*64 + ch)*64 + p;
        P[idx] = make_float2(cx, cy);
        float2 w = W[idx];
        float nx = fmaf(ax, cx, fmaf(-ay, cy, w.x));
        float ny = fmaf(ax, cy, fmaf( ay, cx, w.y));
        cx = nx; cy = ny;
    }
}

__global__ __launch_bounds__(64) void k_scan3(float* __restrict__ zout) {
    int b = blockIdx.x >> 6, ch = blockIdx.x & 63;
    int p = threadIdx.x;
    float ax = g_a[p*2], ay = g_a[p*2+1];
    float2 c = ((float2*)g_pref)[(b*64 + ch)*64 + p];
    size_t off = (((size_t)b*T_ + ch*128) << 7) + 2*p;
    const float* vb = g_vraw + off;
    float* zb = zout + off;
    for (int k = 0; k < 128; k++) {
        *(float2*)(zb + (size_t)k*128) = c;
        float2 w = *(const float2*)(vb + (size_t)k*128);
        float nx = fmaf(ax, c.x, fmaf(-ay, c.y, w.x));
        float ny = fmaf(ax, c.y, fmaf( ay, c.x, w.y));
        c.x = nx; c.y = ny;
    }
}

// ---------------- 11: y-GEMM  y = inv * sum_m pi_m (K21 z + K22 u) ----------------
__global__ __launch_bounds__(256, 2) void k_ygemm(const float* __restrict__ u,
                                                  const float* __restrict__ z,
                                                  const float* __restrict__ K21,
                                                  const float* __restrict__ K22,
                                                  float* __restrict__ y) {
    __shared__ float sxT[32*68];
    __shared__ float sK[32*132];
    int tid = threadIdx.x;
    int tok0 = blockIdx.x * 64;
    float inv = g_scaleArr[1];
    int s0 = (tid >> 4) * 8;
    int t0 = (tid & 15) * 4;
    float acc[4][8] = {};
    for (int jt = 0; jt < 8; jt++) {
        const float* xsrc = (jt < 4) ? z   : u;
        const float* ksrc = (jt < 4) ? K21 : K22;
        int jb = (jt & 3) * 32;
        __syncthreads();
        #pragma unroll
        for (int r = 0; r < 8; r++) {
            int idx = tid + (r << 8);
            int jl = idx & 31, t = idx >> 5;
            sxT[jl*68 + t] = xsrc[((size_t)(tok0 + t) << 7) + jb + jl];
        }
        for (int m = 0; m < 8; m++) {
            __syncthreads();
            #pragma unroll
            for (int r = 0; r < 16; r++) {
                int idx = tid + (r << 8);
                int jl = idx & 31, s = idx >> 5;
                sK[jl*132 + s] = ksrc[((size_t)(m*128 + s) << 7) + jb + jl];
            }
            __syncthreads();
            float part[4][8] = {};
            #pragma unroll 8
            for (int jl = 0; jl < 32; jl++) {
                float4 xv = *(const float4*)&sxT[jl*68 + t0];
                float4 k0 = *(const float4*)&sK[jl*132 + s0];
                float4 k1 = *(const float4*)&sK[jl*132 + s0 + 4];
                float xs[4] = {xv.x, xv.y, xv.z, xv.w};
                float ks[8] = {k0.x,k0.y,k0.z,k0.w,k1.x,k1.y,k1.z,k1.w};
                #pragma unroll
                for (int tt = 0; tt < 4; tt++)
                    #pragma unroll
                    for (int ii = 0; ii < 8; ii++)
                        part[tt][ii] = fmaf(xs[tt], ks[ii], part[tt][ii]);
            }
            #pragma unroll
            for (int tt = 0; tt < 4; tt++) {
                float p = g_pi[(size_t)(tok0 + t0 + tt) * 8 + m];
                #pragma unroll
                for (int ii = 0; ii < 8; ii++)
                    acc[tt][ii] = fmaf(p, part[tt][ii], acc[tt][ii]);
            }
        }
    }
    #pragma unroll
    for (int tt = 0; tt < 4; tt++) {
        float* o = y + ((size_t)(tok0 + t0 + tt) << 7) + s0;
        float4 w0 = {acc[tt][0]*inv, acc[tt][1]*inv, acc[tt][2]*inv, acc[tt][3]*inv};
        float4 w1 = {acc[tt][4]*inv, acc[tt][5]*inv, acc[tt][6]*inv, acc[tt][7]*inv};
        *(float4*)o = w0;
        *(float4*)(o + 4) = w1;
    }
}

// ---------------- launch ----------------
extern "C" void kernel_launch(void* const* d_in, const int* in_sizes, int n_in,
                              void* d_out, int out_size) {
    const float* u       = (const float*)d_in[0];
    const float* rho_raw = (const float*)d_in[1];
    const float* theta   = (const float*)d_in[2];
    const float* K12     = (const float*)d_in[3];
    const float* K21     = (const float*)d_in[4];
    const float* K22     = (const float*)d_in[5];
    const float* gw      = (const float*)d_in[6];
    const float* gb      = (const float*)d_in[7];
    float* y = (float*)d_out;
    float* z = y + (size_t)BT_ * 128;

    k_pairs<<<1, 64>>>(rho_raw, theta);
    k_build<<<8, 256>>>(K12, K21, K22);
    k_G<<<dim3(64, 8), 256>>>();
    k_lanczos<<<8, 256>>>();
    k_scale<<<1, 64>>>();
    k_gate<<<1024, 256>>>(u, gw, gb);
    k_vgemm<<<512, 256>>>(u, K12);
    k_scan1<<<256, 64>>>();
    k_scan2<<<1, 256>>>();
    k_scan3<<<256, 64>>>(z);
    k_ygemm<<<512, 256>>>(u, z, K21, K22, y);
}

// round 8
// speedup vs baseline: 1.9809x; 1.9809x over previous
#include <cuda_runtime.h>
#include <cuda_bf16.h>
#include <mma.h>
#include <math.h>

using namespace nvcuda;

#define B_ 4
#define T_ 8192
#define BT_ (B_*T_)
#define NP_ 64
#define EPS_RADIUS 0.001f
#define NIT 72

// ---------------- device scratch ----------------
__device__ float g_Kfull[8*256*256];
__device__ float g_G[8*256*256];
__device__ float g_lambda[8];
__device__ float g_scaleArr[2];
__device__ float g_pairs[NP_*3];
__device__ float g_a[NP_*2];
__device__ float g_aL[NP_*2];
__device__ float g_pi[(size_t)BT_*8];
__device__ float g_vraw[(size_t)BT_*128];
__device__ float g_W[4*64*64*2];
__device__ float g_pref[4*64*64*2];

// ---------------- reductions ----------------
__device__ __forceinline__ float blkSum(float v, volatile float* red, int tid) {
    #pragma unroll
    for (int o = 16; o; o >>= 1) v += __shfl_xor_sync(0xffffffffu, v, o);
    if ((tid & 31) == 0) red[tid >> 5] = v;
    __syncthreads();
    float r = red[0]+red[1]+red[2]+red[3]+red[4]+red[5]+red[6]+red[7];
    __syncthreads();
    return r;
}
__device__ __forceinline__ float blkMax(float v, volatile float* red, int tid) {
    #pragma unroll
    for (int o = 16; o; o >>= 1) v = fmaxf(v, __shfl_xor_sync(0xffffffffu, v, o));
    if ((tid & 31) == 0) red[tid >> 5] = v;
    __syncthreads();
    float r = red[0];
    #pragma unroll
    for (int k = 1; k < 8; k++) r = fmaxf(r, red[k]);
    __syncthreads();
    return r;
}

// tf32 round-to-nearest (stored back as float bits)
__device__ __forceinline__ float f2tf_f(float f) {
    unsigned r;
    asm("cvt.rna.tf32.f32 %0, %1;" : "=r"(r) : "f"(f));
    return __uint_as_float(r);
}

// ---------------- 1: pair params ----------------
__global__ void k_pairs(const float* __restrict__ rho_raw, const float* __restrict__ theta) {
    int i = threadIdx.x;
    if (i < NP_) {
        float t = 1.f / (1.f + expf(-rho_raw[i]));
        g_pairs[i*3+0] = t * (1.0f - EPS_RADIUS);
        g_pairs[i*3+1] = cosf(theta[i]);
        g_pairs[i*3+2] = sinf(theta[i]);
    }
}

// ---------------- 2: assemble K_raw ----------------
__global__ __launch_bounds__(256) void k_build(const float* __restrict__ K12,
                                               const float* __restrict__ K21,
                                               const float* __restrict__ K22) {
    int e = blockIdx.x;
    int tid = threadIdx.x;
    for (int r = 0; r < 256; r++) {
        int idx = tid + (r << 8);
        int row = idx >> 8;
        int col = idx & 255;
        float val;
        if (row < 128) {
            if (col < 128) {
                val = 0.f;
                int pr = row >> 1;
                if ((col >> 1) == pr) {
                    float rho = g_pairs[pr*3], c = g_pairs[pr*3+1], s = g_pairs[pr*3+2];
                    int ai = row & 1, bi = col & 1;
                    val = (ai == 0) ? (bi == 0 ? rho*c : -rho*s)
                                    : (bi == 0 ? rho*s :  rho*c);
                }
            } else {
                val = K12[((size_t)(e*128 + row) << 7) + (col - 128)];
            }
        } else {
            int r2 = row - 128;
            val = (col < 128) ? K21[((size_t)(e*128 + r2) << 7) + col]
                              : K22[((size_t)(e*128 + r2) << 7) + (col - 128)];
        }
        g_Kfull[((size_t)e << 16) + idx] = val;
    }
}

// ---------------- 3: G = K K^T ----------------
__global__ __launch_bounds__(256) void k_G() {
    __shared__ float sA[32*68], sB[32*68];
    int e = blockIdx.y;
    int ti = blockIdx.x >> 3, tj = blockIdx.x & 7;
    int tid = threadIdx.x;
    const float* Kb = g_Kfull + ((size_t)e << 16);
    int i0 = (tid >> 4) * 2, j0 = (tid & 15) * 2;
    float a00=0.f,a01=0.f,a10=0.f,a11=0.f;
    for (int ks = 0; ks < 4; ks++) {
        __syncthreads();
        #pragma unroll
        for (int r = 0; r < 8; r++) {
            int idx = tid + (r << 8);
            int row = idx >> 6, kk = idx & 63;
            sA[row*68+kk] = Kb[(ti*32+row)*256 + ks*64+kk];
            sB[row*68+kk] = Kb[(tj*32+row)*256 + ks*64+kk];
        }
        __syncthreads();
        #pragma unroll 16
        for (int kk = 0; kk < 64; kk++) {
            float x0 = sA[i0*68+kk],     x1 = sA[(i0+1)*68+kk];
            float y0 = sB[j0*68+kk],     y1 = sB[(j0+1)*68+kk];
            a00 = fmaf(x0,y0,a00); a01 = fmaf(x0,y1,a01);
            a10 = fmaf(x1,y0,a10); a11 = fmaf(x1,y1,a11);
        }
    }
    float* Gb = g_G + ((size_t)e << 16);
    Gb[(ti*32+i0  )*256 + tj*32+j0  ] = a00;
    Gb[(ti*32+i0  )*256 + tj*32+j0+1] = a01;
    Gb[(ti*32+i0+1)*256 + tj*32+j0  ] = a10;
    Gb[(ti*32+i0+1)*256 + tj*32+j0+1] = a11;
}

// ---------------- 4: Lanczos + Sturm ----------------
__global__ __launch_bounds__(256) void k_lanczos() {
    __shared__ __align__(16) float sv[256];
    __shared__ float red[8];
    __shared__ float salpha[NIT], sbeta[NIT];
    int e = blockIdx.x;
    int tid = threadIdx.x;
    const float* Gb = g_G + ((size_t)e << 16);

    unsigned h = (unsigned)tid * 2654435761u ^ ((unsigned)e * 0x9E3779B9u);
    h ^= h >> 13; h *= 0x85ebca6bu; h ^= h >> 16;
    float v = (float)(h & 0xFFFFu) * (1.0f/65536.0f) - 0.5f + 0.0078125f;
    float nr = sqrtf(blkSum(v*v, red, tid));
    v /= nr;
    sv[tid] = v;
    float vprev = 0.f, betap = 0.f;
    int n = NIT;
    for (int it = 0; it < NIT; it++) {
        __syncthreads();
        const float4* row = (const float4*)(Gb + (size_t)tid * 256);
        const float4* sp  = (const float4*)sv;
        float gv = 0.f;
        #pragma unroll 16
        for (int q = 0; q < 64; q++) {
            float4 g = row[q], s = sp[q];
            gv = fmaf(g.x,s.x,gv); gv = fmaf(g.y,s.y,gv);
            gv = fmaf(g.z,s.z,gv); gv = fmaf(g.w,s.w,gv);
        }
        float w = gv - betap * vprev;
        float al = blkSum(v * w, red, tid);
        w -= al * v;
        float b2 = blkSum(w * w, red, tid);
        float bet = sqrtf(b2);
        if (tid == 0) { salpha[it] = al; sbeta[it] = bet; }
        if (bet < 1e-12f) { n = it + 1; break; }
        vprev = v; betap = bet;
        v = w / bet;
        sv[tid] = v;
    }
    __syncthreads();
    float hi = 0.f;
    for (int k = tid; k < n; k += 256) {
        float b0 = (k > 0)     ? sbeta[k-1] : 0.f;
        float b1 = (k < n - 1) ? sbeta[k]   : 0.f;
        hi = fmaxf(hi, salpha[k] + b0 + b1);
    }
    hi = blkMax(hi, red, tid) * 1.0001f + 1e-6f;
    float lo = 0.f;
    for (int round = 0; round < 3; round++) {
        float x = lo + (hi - lo) * ((float)(tid + 1) * (1.0f/257.0f));
        int cnt = 0;
        float d = 1.f;
        for (int k = 0; k < n; k++) {
            float bb = (k > 0) ? sbeta[k-1] : 0.f;
            d = (salpha[k] - x) - bb*bb/d;
            if (d < 0.f) cnt++;
            if (fabsf(d) < 1e-25f) d = -1e-25f;
        }
        float nlo = (cnt <  n) ? x : lo;
        float nhi = (cnt >= n) ? x : hi;
        lo = blkMax(nlo, red, tid);
        hi = -blkMax(-nhi, red, tid);
    }
    if (tid == 0) g_lambda[e] = 0.5f * (lo + hi);
}

// ---------------- 5: scale + poles ----------------
__global__ void k_scale() {
    int i = threadIdx.x;
    float s = 1.0f;
    #pragma unroll
    for (int e = 0; e < 8; e++) s = fmaxf(s, sqrtf(g_lambda[e]));
    if (i == 0) { g_scaleArr[0] = s; g_scaleArr[1] = 1.f / s; }
    if (i < NP_) {
        float inv = 1.f / s;
        float rho = g_pairs[i*3], c = g_pairs[i*3+1], sn = g_pairs[i*3+2];
        float ax = rho * c * inv, ay = rho * sn * inv;
        g_a[i*2+0] = ax; g_a[i*2+1] = ay;
        float px = ax, py = ay;
        #pragma unroll
        for (int q = 0; q < 7; q++) { float nx = px*px - py*py, ny = 2.f*px*py; px = nx; py = ny; }
        g_aL[i*2+0] = px; g_aL[i*2+1] = py;
    }
}

// ---------------- 6: gating softmax ----------------
__global__ __launch_bounds__(256) void k_gate(const float* __restrict__ u,
                                              const float* __restrict__ gw,
                                              const float* __restrict__ gb) {
    __shared__ __align__(16) float sgw[1024];
    __shared__ float sgb[8];
    int tid = threadIdx.x;
    #pragma unroll
    for (int r = 0; r < 4; r++) sgw[tid + (r << 8)] = gw[tid + (r << 8)];
    if (tid < 8) sgb[tid] = gb[tid];
    __syncthreads();
    int tok = blockIdx.x * 32 + (tid >> 3);
    int m = tid & 7;
    const float4* ur = (const float4*)(u + ((size_t)tok << 7));
    const float4* wr = (const float4*)(sgw + (m << 7));
    float acc = sgb[m];
    #pragma unroll 8
    for (int q = 0; q < 32; q++) {
        float4 a = ur[q], w = wr[q];
        acc = fmaf(a.x, w.x, acc); acc = fmaf(a.y, w.y, acc);
        acc = fmaf(a.z, w.z, acc); acc = fmaf(a.w, w.w, acc);
    }
    float mx = acc;
    #pragma unroll
    for (int o = 4; o; o >>= 1) mx = fmaxf(mx, __shfl_xor_sync(0xffffffffu, mx, o));
    float ex = expf(acc - mx);
    float sm = ex;
    #pragma unroll
    for (int o = 4; o; o >>= 1) sm += __shfl_xor_sync(0xffffffffu, sm, o);
    g_pi[(size_t)tok * 8 + m] = ex / sm;
}

// ---------------- 7/11: WMMA tf32 GEMM, pi folded into A ----------------
// C[t,n] = inv * sum_k A[t,k] * Bc[n,k];  k = (m, j), DPE elems per expert.
// A[t,(m,j)] = pi[t,m] * src[t,j]  (src = u for DPE=128;  z|u for DPE=256)
// OUT_VRAW: write to the device symbol g_vraw (device-side address!) instead of
// the 'out' parameter — device symbols must NOT be passed from host code.
#define LDS_ 40
template<int DPE, int KTOT, bool OUT_VRAW>
__global__ __launch_bounds__(256, 2) void k_wmma(const float* __restrict__ u,
                                                 const float* __restrict__ z,
                                                 const float* __restrict__ Kc1,
                                                 const float* __restrict__ Kc2,
                                                 float* __restrict__ out) {
    __shared__ __align__(32) float sA[128*LDS_];
    __shared__ __align__(32) float sB[64*LDS_];
    __shared__ __align__(16) float spi[1024];

    int tid = threadIdx.x;
    int bx = blockIdx.x;
    int tok0 = (bx >> 1) << 7;
    int nout0 = (bx & 1) << 6;
    int wid = tid >> 5;
    int wm = wid & 3, wn = wid >> 2;

    #pragma unroll
    for (int r = 0; r < 4; r++) {
        int i = tid + (r << 8);
        spi[i] = g_pi[((size_t)tok0 << 3) + i];
    }
    __syncthreads();

    float4 aReg[4];
    float4 bReg[2];
    float  aPi[4];
    const int S = KTOT / 32;

    // prefetch slab 0 (m = 0, joff = 0)
    {
        const float* src = (DPE == 128) ? u : z;
        #pragma unroll
        for (int r = 0; r < 4; r++) {
            int idx = tid + (r << 8);
            int t = idx >> 3, c4 = (idx & 7) << 2;
            aReg[r] = *(const float4*)(src + (((size_t)(tok0 + t)) << 7) + c4);
            aPi[r] = spi[t*8];
        }
        #pragma unroll
        for (int r = 0; r < 2; r++) {
            int idx = tid + (r << 8);
            int nn = idx >> 3, c4 = (idx & 7) << 2;
            bReg[r] = *(const float4*)(Kc1 + (((size_t)(nout0 + nn)) << 7) + c4);
        }
    }

    wmma::fragment<wmma::accumulator, 16, 16, 8, float> cf[2][2];
    #pragma unroll
    for (int mi = 0; mi < 2; mi++)
        #pragma unroll
        for (int ni = 0; ni < 2; ni++)
            wmma::fill_fragment(cf[mi][ni], 0.0f);

    for (int s = 0; s < S; s++) {
        if (s > 0) __syncthreads();
        // store current slab (tf32-rounded; A scaled by pi)
        #pragma unroll
        for (int r = 0; r < 4; r++) {
            int idx = tid + (r << 8);
            int t = idx >> 3, c4 = (idx & 7) << 2;
            float p = aPi[r];
            float* d = &sA[t*LDS_ + c4];
            d[0] = f2tf_f(aReg[r].x * p);
            d[1] = f2tf_f(aReg[r].y * p);
            d[2] = f2tf_f(aReg[r].z * p);
            d[3] = f2tf_f(aReg[r].w * p);
        }
        #pragma unroll
        for (int r = 0; r < 2; r++) {
            int idx = tid + (r << 8);
            int nn = idx >> 3, c4 = (idx & 7) << 2;
            float* d = &sB[nn*LDS_ + c4];
            d[0] = f2tf_f(bReg[r].x);
            d[1] = f2tf_f(bReg[r].y);
            d[2] = f2tf_f(bReg[r].z);
            d[3] = f2tf_f(bReg[r].w);
        }
        __syncthreads();

        // prefetch next slab
        if (s + 1 < S) {
            int k0 = (s + 1) << 5;
            int m = k0 / DPE;
            int joff = k0 % DPE;
            const float* src;
            const float* kbase;
            int jb;
            if (DPE == 128) { src = u; kbase = Kc1; jb = joff; }
            else {
                src = (joff < 128) ? z : u;
                kbase = (joff < 128) ? Kc1 : Kc2;
                jb = joff & 127;
            }
            #pragma unroll
            for (int r = 0; r < 4; r++) {
                int idx = tid + (r << 8);
                int t = idx >> 3, c4 = (idx & 7) << 2;
                aReg[r] = *(const float4*)(src + (((size_t)(tok0 + t)) << 7) + jb + c4);
                aPi[r] = spi[t*8 + m];
            }
            #pragma unroll
            for (int r = 0; r < 2; r++) {
                int idx = tid + (r << 8);
                int nn = idx >> 3, c4 = (idx & 7) << 2;
                bReg[r] = *(const float4*)(kbase + (((size_t)(m*128 + nout0 + nn)) << 7) + jb + c4);
            }
        }

        // compute: 4 k-steps of 8
        #pragma unroll
        for (int ks = 0; ks < 4; ks++) {
            int kb = ks << 3;
            wmma::fragment<wmma::matrix_a, 16, 16, 8, wmma::precision::tf32, wmma::row_major> af[2];
            wmma::fragment<wmma::matrix_b, 16, 16, 8, wmma::precision::tf32, wmma::col_major> bf[2];
            wmma::load_matrix_sync(af[0], &sA[(wm*32     )*LDS_ + kb], LDS_);
            wmma::load_matrix_sync(af[1], &sA[(wm*32 + 16)*LDS_ + kb], LDS_);
            wmma::load_matrix_sync(bf[0], &sB[(wn*32     )*LDS_ + kb], LDS_);
            wmma::load_matrix_sync(bf[1], &sB[(wn*32 + 16)*LDS_ + kb], LDS_);
            #pragma unroll
            for (int mi = 0; mi < 2; mi++)
                #pragma unroll
                for (int ni = 0; ni < 2; ni++)
                    wmma::mma_sync(cf[mi][ni], af[mi], bf[ni], cf[mi][ni]);
        }
    }

    float* obase = OUT_VRAW ? g_vraw : out;   // device-side symbol resolution
    float inv = g_scaleArr[1];
    #pragma unroll
    for (int mi = 0; mi < 2; mi++) {
        #pragma unroll
        for (int ni = 0; ni < 2; ni++) {
            #pragma unroll
            for (int q = 0; q < cf[mi][ni].num_elements; q++) cf[mi][ni].x[q] *= inv;
            int row0 = tok0 + wm*32 + mi*16;
            int col0 = nout0 + wn*32 + ni*16;
            wmma::store_matrix_sync(obase + ((size_t)row0 << 7) + col0, cf[mi][ni], 128, wmma::mem_row_major);
        }
    }
}

// ---------------- 8-10: chunked complex scan ----------------
__global__ __launch_bounds__(64) void k_scan1() {
    int b = blockIdx.x >> 6, ch = blockIdx.x & 63;
    int p = threadIdx.x;
    float ax = g_a[p*2], ay = g_a[p*2+1];
    float cx = 0.f, cy = 0.f;
    const float* base = g_vraw + (((size_t)b*T_ + ch*128) << 7) + 2*p;
    for (int k = 0; k < 128; k++) {
        float2 w = *(const float2*)(base + (size_t)k*128);
        float nx = fmaf(ax, cx, fmaf(-ay, cy, w.x));
        float ny = fmaf(ax, cy, fmaf( ay, cx, w.y));
        cx = nx; cy = ny;
    }
    ((float2*)g_W)[(b*64 + ch)*64 + p] = make_float2(cx, cy);
}

__global__ __launch_bounds__(256) void k_scan2() {
    int tid = threadIdx.x;
    int b = tid >> 6, p = tid & 63;
    float ax = g_aL[p*2], ay = g_aL[p*2+1];
    float cx = 0.f, cy = 0.f;
    float2* W = (float2*)g_W;
    float2* P = (float2*)g_pref;
    for (int ch = 0; ch < 64; ch++) {
        int idx = (b*64 + ch)*64 + p;
        P[idx] = make_float2(cx, cy);
        float2 w = W[idx];
        float nx = fmaf(ax, cx, fmaf(-ay, cy, w.x));
        float ny = fmaf(ax, cy, fmaf( ay, cx, w.y));
        cx = nx; cy = ny;
    }
}

__global__ __launch_bounds__(64) void k_scan3(float* __restrict__ zout) {
    int b = blockIdx.x >> 6, ch = blockIdx.x & 63;
    int p = threadIdx.x;
    float ax = g_a[p*2], ay = g_a[p*2+1];
    float2 c = ((float2*)g_pref)[(b*64 + ch)*64 + p];
    size_t off = (((size_t)b*T_ + ch*128) << 7) + 2*p;
    const float* vb = g_vraw + off;
    float* zb = zout + off;
    for (int k = 0; k < 128; k++) {
        *(float2*)(zb + (size_t)k*128) = c;
        float2 w = *(const float2*)(vb + (size_t)k*128);
        float nx = fmaf(ax, c.x, fmaf(-ay, c.y, w.x));
        float ny = fmaf(ax, c.y, fmaf( ay, c.x, w.y));
        c.x = nx; c.y = ny;
    }
}

// ---------------- launch ----------------
extern "C" void kernel_launch(void* const* d_in, const int* in_sizes, int n_in,
                              void* d_out, int out_size) {
    const float* u       = (const float*)d_in[0];
    const float* rho_raw = (const float*)d_in[1];
    const float* theta   = (const float*)d_in[2];
    const float* K12     = (const float*)d_in[3];
    const float* K21     = (const float*)d_in[4];
    const float* K22     = (const float*)d_in[5];
    const float* gw      = (const float*)d_in[6];
    const float* gb      = (const float*)d_in[7];
    float* y = (float*)d_out;
    float* z = y + (size_t)BT_ * 128;

    k_pairs<<<1, 64>>>(rho_raw, theta);
    k_build<<<8, 256>>>(K12, K21, K22);
    k_G<<<dim3(64, 8), 256>>>();
    k_lanczos<<<8, 256>>>();
    k_scale<<<1, 64>>>();
    k_gate<<<1024, 256>>>(u, gw, gb);
    k_wmma<128, 1024, true><<<512, 256>>>(u, (const float*)0, K12, (const float*)0, (float*)0);
    k_scan1<<<256, 64>>>();
    k_scan2<<<1, 256>>>();
    k_scan3<<<256, 64>>>(z);
    k_wmma<256, 2048, false><<<512, 256>>>(u, z, K21, K22, y);
}

// round 16
// speedup vs baseline: 1.9934x; 1.0063x over previous
#include <cuda_runtime.h>
#include <cuda_bf16.h>
#include <mma.h>
#include <math.h>

using namespace nvcuda;

#define B_ 4
#define T_ 8192
#define BT_ (B_*T_)
#define NP_ 64
#define EPS_RADIUS 0.001f
#define NIT 72

// ---------------- device scratch ----------------
__device__ float g_Kfull[8*256*256];
__device__ float g_G[8*256*256];
__device__ float g_lambda[8];
__device__ float g_scaleArr[2];
__device__ float g_pairs[NP_*3];
__device__ float g_a[NP_*2];
__device__ float g_aL[NP_*2];
__device__ float g_pi[(size_t)BT_*8];
__device__ float g_vraw[(size_t)BT_*128];
__device__ float g_W[4*64*64*2];
__device__ float g_pref[4*64*64*2];

// ---------------- reductions ----------------
__device__ __forceinline__ float blkSum(float v, volatile float* red, int tid) {
    #pragma unroll
    for (int o = 16; o; o >>= 1) v += __shfl_xor_sync(0xffffffffu, v, o);
    if ((tid & 31) == 0) red[tid >> 5] = v;
    __syncthreads();
    float r = red[0]+red[1]+red[2]+red[3]+red[4]+red[5]+red[6]+red[7];
    __syncthreads();
    return r;
}
__device__ __forceinline__ float blkMax(float v, volatile float* red, int tid) {
    #pragma unroll
    for (int o = 16; o; o >>= 1) v = fmaxf(v, __shfl_xor_sync(0xffffffffu, v, o));
    if ((tid & 31) == 0) red[tid >> 5] = v;
    __syncthreads();
    float r = red[0];
    #pragma unroll
    for (int k = 1; k < 8; k++) r = fmaxf(r, red[k]);
    __syncthreads();
    return r;
}

// tf32 round-to-nearest (stored back as float bits)
__device__ __forceinline__ float f2tf_f(float f) {
    unsigned r;
    asm("cvt.rna.tf32.f32 %0, %1;" : "=r"(r) : "f"(f));
    return __uint_as_float(r);
}

// ---------------- 1: pair params ----------------
__global__ void k_pairs(const float* __restrict__ rho_raw, const float* __restrict__ theta) {
    int i = threadIdx.x;
    if (i < NP_) {
        float t = 1.f / (1.f + expf(-rho_raw[i]));
        g_pairs[i*3+0] = t * (1.0f - EPS_RADIUS);
        g_pairs[i*3+1] = cosf(theta[i]);
        g_pairs[i*3+2] = sinf(theta[i]);
    }
}

// ---------------- 2: assemble K_raw ----------------
__global__ __launch_bounds__(256) void k_build(const float* __restrict__ K12,
                                               const float* __restrict__ K21,
                                               const float* __restrict__ K22) {
    int e = blockIdx.x;
    int tid = threadIdx.x;
    for (int r = 0; r < 256; r++) {
        int idx = tid + (r << 8);
        int row = idx >> 8;
        int col = idx & 255;
        float val;
        if (row < 128) {
            if (col < 128) {
                val = 0.f;
                int pr = row >> 1;
                if ((col >> 1) == pr) {
                    float rho = g_pairs[pr*3], c = g_pairs[pr*3+1], s = g_pairs[pr*3+2];
                    int ai = row & 1, bi = col & 1;
                    val = (ai == 0) ? (bi == 0 ? rho*c : -rho*s)
                                    : (bi == 0 ? rho*s :  rho*c);
                }
            } else {
                val = K12[((size_t)(e*128 + row) << 7) + (col - 128)];
            }
        } else {
            int r2 = row - 128;
            val = (col < 128) ? K21[((size_t)(e*128 + r2) << 7) + col]
                              : K22[((size_t)(e*128 + r2) << 7) + (col - 128)];
        }
        g_Kfull[((size_t)e << 16) + idx] = val;
    }
}

// ---------------- 3: G = K K^T ----------------
__global__ __launch_bounds__(256) void k_G() {
    __shared__ float sA[32*68], sB[32*68];
    int e = blockIdx.y;
    int ti = blockIdx.x >> 3, tj = blockIdx.x & 7;
    int tid = threadIdx.x;
    const float* Kb = g_Kfull + ((size_t)e << 16);
    int i0 = (tid >> 4) * 2, j0 = (tid & 15) * 2;
    float a00=0.f,a01=0.f,a10=0.f,a11=0.f;
    for (int ks = 0; ks < 4; ks++) {
        __syncthreads();
        #pragma unroll
        for (int r = 0; r < 8; r++) {
            int idx = tid + (r << 8);
            int row = idx >> 6, kk = idx & 63;
            sA[row*68+kk] = Kb[(ti*32+row)*256 + ks*64+kk];
            sB[row*68+kk] = Kb[(tj*32+row)*256 + ks*64+kk];
        }
        __syncthreads();
        #pragma unroll 16
        for (int kk = 0; kk < 64; kk++) {
            float x0 = sA[i0*68+kk],     x1 = sA[(i0+1)*68+kk];
            float y0 = sB[j0*68+kk],     y1 = sB[(j0+1)*68+kk];
            a00 = fmaf(x0,y0,a00); a01 = fmaf(x0,y1,a01);
            a10 = fmaf(x1,y0,a10); a11 = fmaf(x1,y1,a11);
        }
    }
    float* Gb = g_G + ((size_t)e << 16);
    Gb[(ti*32+i0  )*256 + tj*32+j0  ] = a00;
    Gb[(ti*32+i0  )*256 + tj*32+j0+1] = a01;
    Gb[(ti*32+i0+1)*256 + tj*32+j0  ] = a10;
    Gb[(ti*32+i0+1)*256 + tj*32+j0+1] = a11;
}

// ---------------- 4: Lanczos + Sturm (batched-MLP matvec) ----------------
__global__ __launch_bounds__(256) void k_lanczos() {
    __shared__ __align__(16) float sv[256];
    __shared__ float red[8];
    __shared__ float salpha[NIT], sbeta[NIT];
    int e = blockIdx.x;
    int tid = threadIdx.x;
    const float* Gb = g_G + ((size_t)e << 16);

    unsigned h = (unsigned)tid * 2654435761u ^ ((unsigned)e * 0x9E3779B9u);
    h ^= h >> 13; h *= 0x85ebca6bu; h ^= h >> 16;
    float v = (float)(h & 0xFFFFu) * (1.0f/65536.0f) - 0.5f + 0.0078125f;
    float nr = sqrtf(blkSum(v*v, red, tid));
    v /= nr;
    sv[tid] = v;
    float vprev = 0.f, betap = 0.f;
    int n = NIT;
    const float4* row = (const float4*)(Gb + (size_t)tid * 256);
    for (int it = 0; it < NIT; it++) {
        __syncthreads();
        const float4* sp = (const float4*)sv;
        // batched loads: 4 groups of 16 float4 in flight (MLP~16)
        float gv0 = 0.f, gv1 = 0.f, gv2 = 0.f, gv3 = 0.f;
        #pragma unroll
        for (int grp = 0; grp < 4; grp++) {
            float4 gbuf[16];
            #pragma unroll
            for (int i = 0; i < 16; i++) gbuf[i] = row[grp*16 + i];
            #pragma unroll
            for (int i = 0; i < 16; i++) {
                float4 s = sp[grp*16 + i];
                float4 g = gbuf[i];
                if ((i & 3) == 0)      { gv0 = fmaf(g.x,s.x,gv0); gv0 = fmaf(g.y,s.y,gv0); gv0 = fmaf(g.z,s.z,gv0); gv0 = fmaf(g.w,s.w,gv0); }
                else if ((i & 3) == 1) { gv1 = fmaf(g.x,s.x,gv1); gv1 = fmaf(g.y,s.y,gv1); gv1 = fmaf(g.z,s.z,gv1); gv1 = fmaf(g.w,s.w,gv1); }
                else if ((i & 3) == 2) { gv2 = fmaf(g.x,s.x,gv2); gv2 = fmaf(g.y,s.y,gv2); gv2 = fmaf(g.z,s.z,gv2); gv2 = fmaf(g.w,s.w,gv2); }
                else                   { gv3 = fmaf(g.x,s.x,gv3); gv3 = fmaf(g.y,s.y,gv3); gv3 = fmaf(g.z,s.z,gv3); gv3 = fmaf(g.w,s.w,gv3); }
            }
        }
        float gv = (gv0 + gv1) + (gv2 + gv3);
        float w = gv - betap * vprev;
        float al = blkSum(v * w, red, tid);
        w -= al * v;
        float b2 = blkSum(w * w, red, tid);
        float bet = sqrtf(b2);
        if (tid == 0) { salpha[it] = al; sbeta[it] = bet; }
        if (bet < 1e-12f) { n = it + 1; break; }
        vprev = v; betap = bet;
        v = w / bet;
        sv[tid] = v;
    }
    __syncthreads();
    float hi = 0.f;
    for (int k = tid; k < n; k += 256) {
        float b0 = (k > 0)     ? sbeta[k-1] : 0.f;
        float b1 = (k < n - 1) ? sbeta[k]   : 0.f;
        hi = fmaxf(hi, salpha[k] + b0 + b1);
    }
    hi = blkMax(hi, red, tid) * 1.0001f + 1e-6f;
    float lo = 0.f;
    for (int round = 0; round < 3; round++) {
        float x = lo + (hi - lo) * ((float)(tid + 1) * (1.0f/257.0f));
        int cnt = 0;
        float d = 1.f;
        for (int k = 0; k < n; k++) {
            float bb = (k > 0) ? sbeta[k-1] : 0.f;
            d = (salpha[k] - x) - bb*bb/d;
            if (d < 0.f) cnt++;
            if (fabsf(d) < 1e-25f) d = -1e-25f;
        }
        float nlo = (cnt <  n) ? x : lo;
        float nhi = (cnt >= n) ? x : hi;
        lo = blkMax(nlo, red, tid);
        hi = -blkMax(-nhi, red, tid);
    }
    if (tid == 0) g_lambda[e] = 0.5f * (lo + hi);
}

// ---------------- 5: scale + poles ----------------
__global__ void k_scale() {
    int i = threadIdx.x;
    float s = 1.0f;
    #pragma unroll
    for (int e = 0; e < 8; e++) s = fmaxf(s, sqrtf(g_lambda[e]));
    if (i == 0) { g_scaleArr[0] = s; g_scaleArr[1] = 1.f / s; }
    if (i < NP_) {
        float inv = 1.f / s;
        float rho = g_pairs[i*3], c = g_pairs[i*3+1], sn = g_pairs[i*3+2];
        float ax = rho * c * inv, ay = rho * sn * inv;
        g_a[i*2+0] = ax; g_a[i*2+1] = ay;
        float px = ax, py = ay;
        #pragma unroll
        for (int q = 0; q < 7; q++) { float nx = px*px - py*py, ny = 2.f*px*py; px = nx; py = ny; }
        g_aL[i*2+0] = px; g_aL[i*2+1] = py;
    }
}

// ---------------- 6: gating softmax ----------------
__global__ __launch_bounds__(256) void k_gate(const float* __restrict__ u,
                                              const float* __restrict__ gw,
                                              const float* __restrict__ gb) {
    __shared__ __align__(16) float sgw[1024];
    __shared__ float sgb[8];
    int tid = threadIdx.x;
    #pragma unroll
    for (int r = 0; r < 4; r++) sgw[tid + (r << 8)] = gw[tid + (r << 8)];
    if (tid < 8) sgb[tid] = gb[tid];
    __syncthreads();
    int tok = blockIdx.x * 32 + (tid >> 3);
    int m = tid & 7;
    const float4* ur = (const float4*)(u + ((size_t)tok << 7));
    const float4* wr = (const float4*)(sgw + (m << 7));
    float acc = sgb[m];
    #pragma unroll 8
    for (int q = 0; q < 32; q++) {
        float4 a = ur[q], w = wr[q];
        acc = fmaf(a.x, w.x, acc); acc = fmaf(a.y, w.y, acc);
        acc = fmaf(a.z, w.z, acc); acc = fmaf(a.w, w.w, acc);
    }
    float mx = acc;
    #pragma unroll
    for (int o = 4; o; o >>= 1) mx = fmaxf(mx, __shfl_xor_sync(0xffffffffu, mx, o));
    float ex = expf(acc - mx);
    float sm = ex;
    #pragma unroll
    for (int o = 4; o; o >>= 1) sm += __shfl_xor_sync(0xffffffffu, sm, o);
    g_pi[(size_t)tok * 8 + m] = ex / sm;
}

// ---------------- 7/11: WMMA tf32 GEMM, pi folded into A ----------------
// C[t,n] = inv * sum_k A[t,k] * Bc[n,k];  k = (m, j), DPE elems per expert.
// A[t,(m,j)] = pi[t,m] * src[t,j]  (src = u for DPE=128;  z|u for DPE=256)
// OUT_VRAW: write to the device symbol g_vraw (device-side address!) instead of
// the 'out' parameter — device symbols must NOT be passed from host code.
#define LDS_ 40
template<int DPE, int KTOT, bool OUT_VRAW>
__global__ __launch_bounds__(256, 2) void k_wmma(const float* __restrict__ u,
                                                 const float* __restrict__ z,
                                                 const float* __restrict__ Kc1,
                                                 const float* __restrict__ Kc2,
                                                 float* __restrict__ out) {
    __shared__ __align__(32) float sA[128*LDS_];
    __shared__ __align__(32) float sB[64*LDS_];
    __shared__ __align__(16) float spi[1024];

    int tid = threadIdx.x;
    int bx = blockIdx.x;
    int tok0 = (bx >> 1) << 7;
    int nout0 = (bx & 1) << 6;
    int wid = tid >> 5;
    int wm = wid & 3, wn = wid >> 2;

    #pragma unroll
    for (int r = 0; r < 4; r++) {
        int i = tid + (r << 8);
        spi[i] = g_pi[((size_t)tok0 << 3) + i];
    }
    __syncthreads();

    float4 aReg[4];
    float4 bReg[2];
    float  aPi[4];
    const int S = KTOT / 32;

    // prefetch slab 0 (m = 0, joff = 0)
    {
        const float* src = (DPE == 128) ? u : z;
        #pragma unroll
        for (int r = 0; r < 4; r++) {
            int idx = tid + (r << 8);
            int t = idx >> 3, c4 = (idx & 7) << 2;
            aReg[r] = *(const float4*)(src + (((size_t)(tok0 + t)) << 7) + c4);
            aPi[r] = spi[t*8];
        }
        #pragma unroll
        for (int r = 0; r < 2; r++) {
            int idx = tid + (r << 8);
            int nn = idx >> 3, c4 = (idx & 7) << 2;
            bReg[r] = *(const float4*)(Kc1 + (((size_t)(nout0 + nn)) << 7) + c4);
        }
    }

    wmma::fragment<wmma::accumulator, 16, 16, 8, float> cf[2][2];
    #pragma unroll
    for (int mi = 0; mi < 2; mi++)
        #pragma unroll
        for (int ni = 0; ni < 2; ni++)
            wmma::fill_fragment(cf[mi][ni], 0.0f);

    for (int s = 0; s < S; s++) {
        if (s > 0) __syncthreads();
        // store current slab (tf32-rounded; A scaled by pi)
        #pragma unroll
        for (int r = 0; r < 4; r++) {
            int idx = tid + (r << 8);
            int t = idx >> 3, c4 = (idx & 7) << 2;
            float p = aPi[r];
            float* d = &sA[t*LDS_ + c4];
            d[0] = f2tf_f(aReg[r].x * p);
            d[1] = f2tf_f(aReg[r].y * p);
            d[2] = f2tf_f(aReg[r].z * p);
            d[3] = f2tf_f(aReg[r].w * p);
        }
        #pragma unroll
        for (int r = 0; r < 2; r++) {
            int idx = tid + (r << 8);
            int nn = idx >> 3, c4 = (idx & 7) << 2;
            float* d = &sB[nn*LDS_ + c4];
            d[0] = f2tf_f(bReg[r].x);
            d[1] = f2tf_f(bReg[r].y);
            d[2] = f2tf_f(bReg[r].z);
            d[3] = f2tf_f(bReg[r].w);
        }
        __syncthreads();

        // prefetch next slab
        if (s + 1 < S) {
            int k0 = (s + 1) << 5;
            int m = k0 / DPE;
            int joff = k0 % DPE;
            const float* src;
            const float* kbase;
            int jb;
            if (DPE == 128) { src = u; kbase = Kc1; jb = joff; }
            else {
                src = (joff < 128) ? z : u;
                kbase = (joff < 128) ? Kc1 : Kc2;
                jb = joff & 127;
            }
            #pragma unroll
            for (int r = 0; r < 4; r++) {
                int idx = tid + (r << 8);
                int t = idx >> 3, c4 = (idx & 7) << 2;
                aReg[r] = *(const float4*)(src + (((size_t)(tok0 + t)) << 7) + jb + c4);
                aPi[r] = spi[t*8 + m];
            }
            #pragma unroll
            for (int r = 0; r < 2; r++) {
                int idx = tid + (r << 8);
                int nn = idx >> 3, c4 = (idx & 7) << 2;
                bReg[r] = *(const float4*)(kbase + (((size_t)(m*128 + nout0 + nn)) << 7) + jb + c4);
            }
        }

        // compute: 4 k-steps of 8
        #pragma unroll
        for (int ks = 0; ks < 4; ks++) {
            int kb = ks << 3;
            wmma::fragment<wmma::matrix_a, 16, 16, 8, wmma::precision::tf32, wmma::row_major> af[2];
            wmma::fragment<wmma::matrix_b, 16, 16, 8, wmma::precision::tf32, wmma::col_major> bf[2];
            wmma::load_matrix_sync(af[0], &sA[(wm*32     )*LDS_ + kb], LDS_);
            wmma::load_matrix_sync(af[1], &sA[(wm*32 + 16)*LDS_ + kb], LDS_);
            wmma::load_matrix_sync(bf[0], &sB[(wn*32     )*LDS_ + kb], LDS_);
            wmma::load_matrix_sync(bf[1], &sB[(wn*32 + 16)*LDS_ + kb], LDS_);
            #pragma unroll
            for (int mi = 0; mi < 2; mi++)
                #pragma unroll
                for (int ni = 0; ni < 2; ni++)
                    wmma::mma_sync(cf[mi][ni], af[mi], bf[ni], cf[mi][ni]);
        }
    }

    float* obase = OUT_VRAW ? g_vraw : out;   // device-side symbol resolution
    float inv = g_scaleArr[1];
    #pragma unroll
    for (int mi = 0; mi < 2; mi++) {
        #pragma unroll
        for (int ni = 0; ni < 2; ni++) {
            #pragma unroll
            for (int q = 0; q < cf[mi][ni].num_elements; q++) cf[mi][ni].x[q] *= inv;
            int row0 = tok0 + wm*32 + mi*16;
            int col0 = nout0 + wn*32 + ni*16;
            wmma::store_matrix_sync(obase + ((size_t)row0 << 7) + col0, cf[mi][ni], 128, wmma::mem_row_major);
        }
    }
}

// ---------------- 8-10: chunked complex scan ----------------
__global__ __launch_bounds__(64) void k_scan1() {
    int b = blockIdx.x >> 6, ch = blockIdx.x & 63;
    int p = threadIdx.x;
    float ax = g_a[p*2], ay = g_a[p*2+1];
    float cx = 0.f, cy = 0.f;
    const float* base = g_vraw + (((size_t)b*T_ + ch*128) << 7) + 2*p;
    for (int k = 0; k < 128; k++) {
        float2 w = *(const float2*)(base + (size_t)k*128);
        float nx = fmaf(ax, cx, fmaf(-ay, cy, w.x));
        float ny = fmaf(ax, cy, fmaf( ay, cx, w.y));
        cx = nx; cy = ny;
    }
    ((float2*)g_W)[(b*64 + ch)*64 + p] = make_float2(cx, cy);
}

__global__ __launch_bounds__(256) void k_scan2() {
    int tid = threadIdx.x;
    int b = tid >> 6, p = tid & 63;
    float ax = g_aL[p*2], ay = g_aL[p*2+1];
    float cx = 0.f, cy = 0.f;
    float2* W = (float2*)g_W;
    float2* P = (float2*)g_pref;
    for (int ch = 0; ch < 64; ch++) {
        int idx = (b*64 + ch)*64 + p;
        P[idx] = make_float2(cx, cy);
        float2 w = W[idx];
        float nx = fmaf(ax, cx, fmaf(-ay, cy, w.x));
        float ny = fmaf(ax, cy, fmaf( ay, cx, w.y));
        cx = nx; cy = ny;
    }
}

__global__ __launch_bounds__(64) void k_scan3(float* __restrict__ zout) {
    int b = blockIdx.x >> 6, ch = blockIdx.x & 63;
    int p = threadIdx.x;
    float ax = g_a[p*2], ay = g_a[p*2+1];
    float2 c = ((float2*)g_pref)[(b*64 + ch)*64 + p];
    size_t off = (((size_t)b*T_ + ch*128) << 7) + 2*p;
    const float* vb = g_vraw + off;
    float* zb = zout + off;
    for (int k = 0; k < 128; k++) {
        *(float2*)(zb + (size_t)k*128) = c;
        float2 w = *(const float2*)(vb + (size_t)k*128);
        float nx = fmaf(ax, c.x, fmaf(-ay, c.y, w.x));
        float ny = fmaf(ax, c.y, fmaf( ay, c.x, w.y));
        c.x = nx; c.y = ny;
    }
}

// ---------------- launch ----------------
extern "C" void kernel_launch(void* const* d_in, const int* in_sizes, int n_in,
                              void* d_out, int out_size) {
    const float* u       = (const float*)d_in[0];
    const float* rho_raw = (const float*)d_in[1];
    const float* theta   = (const float*)d_in[2];
    const float* K12     = (const float*)d_in[3];
    const float* K21     = (const float*)d_in[4];
    const float* K22     = (const float*)d_in[5];
    const float* gw      = (const float*)d_in[6];
    const float* gb      = (const float*)d_in[7];
    float* y = (float*)d_out;
    float* z = y + (size_t)BT_ * 128;

    k_pairs<<<1, 64>>>(rho_raw, theta);
    k_build<<<8, 256>>>(K12, K21, K22);
    k_G<<<dim3(64, 8), 256>>>();
    k_lanczos<<<8, 256>>>();
    k_scale<<<1, 64>>>();
    k_gate<<<1024, 256>>>(u, gw, gb);
    k_wmma<128, 1024, true><<<512, 256>>>(u, (const float*)0, K12, (const float*)0, (float*)0);
    k_scan1<<<256, 64>>>();
    k_scan2<<<1, 256>>>();
    k_scan3<<<256, 64>>>(z);
    k_wmma<256, 2048, false><<<512, 256>>>(u, z, K21, K22, y);
}